// round 11
// baseline (speedup 1.0000x reference)
#include <cuda_runtime.h>
#include <cuda_fp16.h>
#include <cstdint>

// ---------------------------------------------------------------------------
// LayerNormDenseGeneral: out = LN(x) @ (kernel + lora_a@lora_b) + bias
// M=8192, K=H=4096, N=F=4096, R=32
// compute_103 build (no tcgen05). fp16 mma.sync m16n8k16 + ldmatrix.x4.
// R11: persistent GEMM (grid=296, ~7 tiles/CTA). Chunk stream flattened
// across tiles; producer lookahead (+2 chunks) crosses tile boundaries so
// next tile's loads overlap this tile's epilogue. Removes wave quantization
// and per-tile pipeline refill. Consumer math identical to R10 (655us).
// ---------------------------------------------------------------------------

#define H_DIM 4096
#define F_DIM 4096
#define M_DIM 8192

#define BM 128
#define BN 128
#define BK 64
#define NCHUNK (H_DIM / BK)                   // 64
#define NTILES 2048                           // (8192/128)*(4096/128)
#define GRID 296                              // 2 * 148 SMs
#define TILE_BYTES 16384                      // 128 rows * 128 B
#define A_STAGE_BYTES TILE_BYTES
#define STAGE_BYTES (2 * TILE_BYTES)          // 32768 (A + B)
#define NSTAGE 3
#define MBAR_OFF (NSTAGE * STAGE_BYTES)       // 98304
#define GEMM_SMEM (MBAR_OFF + 64)             // 98368 -> 2 CTAs/SM
#define STAGE_TX 32768u

__device__ __align__(16) __half g_Y[(size_t)M_DIM * H_DIM];   // tiled+swizzled
__device__ __align__(16) __half g_WT[(size_t)F_DIM * H_DIM];  // tiled+swizzled

// ---------------------------------------------------------------------------
__device__ __forceinline__ uint32_t smem_u32(const void* p) {
    uint32_t a;
    asm("{ .reg .u64 t; cvta.to.shared.u64 t, %1; cvt.u32.u64 %0, t; }"
        : "=r"(a) : "l"(p));
    return a;
}

__device__ __forceinline__ void ldsm_x4(uint32_t* r, uint32_t addr) {
    asm volatile("ldmatrix.sync.aligned.m8n8.x4.shared.b16 {%0,%1,%2,%3}, [%4];"
                 : "=r"(r[0]), "=r"(r[1]), "=r"(r[2]), "=r"(r[3]) : "r"(addr));
}

__device__ __forceinline__ uint32_t packh2(float lo, float hi) {
    __half2 h = __floats2half2_rn(lo, hi);
    return *reinterpret_cast<uint32_t*>(&h);
}

__device__ __forceinline__ void mma_f16(float* d,
                                        uint32_t a0, uint32_t a1,
                                        uint32_t a2, uint32_t a3,
                                        uint32_t b0, uint32_t b1) {
    asm volatile(
        "mma.sync.aligned.m16n8k16.row.col.f32.f16.f16.f32 "
        "{%0,%1,%2,%3}, {%4,%5,%6,%7}, {%8,%9}, {%0,%1,%2,%3};"
        : "+f"(d[0]), "+f"(d[1]), "+f"(d[2]), "+f"(d[3])
        : "r"(a0), "r"(a1), "r"(a2), "r"(a3), "r"(b0), "r"(b1));
}

__device__ __forceinline__ void bulk_cp(uint32_t dst, const void* src,
                                        uint32_t bytes, uint32_t mbar) {
    asm volatile(
        "cp.async.bulk.shared::cluster.global.mbarrier::complete_tx::bytes "
        "[%0], [%1], %2, [%3];"
        :: "r"(dst), "l"(__cvta_generic_to_global(src)), "r"(bytes), "r"(mbar)
        : "memory");
}

#define MBAR_INIT(addr, cnt) \
    asm volatile("mbarrier.init.shared.b64 [%0], %1;" :: "r"(addr), "r"(cnt) : "memory")

#define MBAR_WAIT(addr, parity) do {                                         \
    uint32_t _m = (addr); uint32_t _p = (parity); uint32_t _d;               \
    asm volatile(                                                            \
        "{\n\t.reg .pred p;\n\t"                                             \
        "mbarrier.try_wait.parity.acquire.cta.shared::cta.b64 p, [%1], %2;\n\t" \
        "selp.b32 %0, 1, 0, p;\n\t}"                                         \
        : "=r"(_d) : "r"(_m), "r"(_p) : "memory");                           \
    if (!_d) {                                                               \
        asm volatile(                                                        \
            "{\n\t.reg .pred P1;\n\t"                                        \
            "WL_%=:\n\t"                                                     \
            "mbarrier.try_wait.parity.acquire.cta.shared::cta.b64 P1, [%0], %1, 0x989680;\n\t" \
            "@P1 bra.uni WD_%=;\n\t"                                         \
            "bra.uni WL_%=;\n\t"                                             \
            "WD_%=:\n\t}"                                                    \
            :: "r"(_m), "r"(_p) : "memory");                                 \
    }                                                                        \
} while (0)

// ---------------------------------------------------------------------------
// Kernel 1: LayerNorm rows of x -> g_Y (fp16, tiled + swizzled layout)
// ---------------------------------------------------------------------------
__global__ __launch_bounds__(256, 1)
void ln_kernel(const float* __restrict__ x, const float* __restrict__ gamma,
               const float* __restrict__ beta) {
    __shared__ float sm[8];
    const int row = blockIdx.x;
    const float4* xr = reinterpret_cast<const float4*>(x) + (size_t)row * (H_DIM / 4);
    float4 v[2][2];
    float s = 0.f;
#pragma unroll
    for (int i = 0; i < 2; i++) {
        int q = (threadIdx.x + i * 256) * 2;
        v[i][0] = xr[q];
        v[i][1] = xr[q + 1];
        s += (v[i][0].x + v[i][0].y) + (v[i][0].z + v[i][0].w);
        s += (v[i][1].x + v[i][1].y) + (v[i][1].z + v[i][1].w);
    }
#pragma unroll
    for (int o = 16; o > 0; o >>= 1) s += __shfl_xor_sync(0xffffffffu, s, o);
    if ((threadIdx.x & 31) == 0) sm[threadIdx.x >> 5] = s;
    __syncthreads();
    float tot = 0.f;
#pragma unroll
    for (int k = 0; k < 8; k++) tot += sm[k];
    float mean = tot * (1.0f / H_DIM);
    __syncthreads();

    float s2 = 0.f;
#pragma unroll
    for (int i = 0; i < 2; i++)
#pragma unroll
        for (int h = 0; h < 2; h++) {
            float a = v[i][h].x - mean, b = v[i][h].y - mean;
            float c = v[i][h].z - mean, d = v[i][h].w - mean;
            s2 += (a * a + b * b) + (c * c + d * d);
        }
#pragma unroll
    for (int o = 16; o > 0; o >>= 1) s2 += __shfl_xor_sync(0xffffffffu, s2, o);
    if ((threadIdx.x & 31) == 0) sm[threadIdx.x >> 5] = s2;
    __syncthreads();
    float t2 = 0.f;
#pragma unroll
    for (int k = 0; k < 8; k++) t2 += sm[k];
    float rstd = rsqrtf(t2 * (1.0f / H_DIM) + 1e-6f);

    const float4* g4 = reinterpret_cast<const float4*>(gamma);
    const float4* b4 = reinterpret_cast<const float4*>(beta);
    char* base = reinterpret_cast<char*>(g_Y);
    const size_t tr = (size_t)(row >> 7) * 64;
    const uint32_t rowoff = (uint32_t)(row & 127) * 128;
    const uint32_t rswz = (uint32_t)(row & 7) << 4;
#pragma unroll
    for (int i = 0; i < 2; i++) {
        int q = (threadIdx.x + i * 256) * 2;
        int k0 = q * 4;
        float4 g0 = g4[q], g1 = g4[q + 1];
        float4 c0 = b4[q], c1 = b4[q + 1];
        uint4 o;
        o.x = packh2((v[i][0].x - mean) * rstd * g0.x + c0.x,
                     (v[i][0].y - mean) * rstd * g0.y + c0.y);
        o.y = packh2((v[i][0].z - mean) * rstd * g0.z + c0.z,
                     (v[i][0].w - mean) * rstd * g0.w + c0.w);
        o.z = packh2((v[i][1].x - mean) * rstd * g1.x + c1.x,
                     (v[i][1].y - mean) * rstd * g1.y + c1.y);
        o.w = packh2((v[i][1].z - mean) * rstd * g1.z + c1.z,
                     (v[i][1].w - mean) * rstd * g1.w + c1.w);
        int j = k0 >> 6;
        uint32_t off = (rowoff + (uint32_t)(k0 & 63) * 2) ^ rswz;
        *reinterpret_cast<uint4*>(base + ((tr + j) << 14) + off) = o;
    }
}

// ---------------------------------------------------------------------------
// Kernel 2: g_WT tiles = fp16( kernel^T + (lora_a@lora_b)^T ), swizzled.
// ---------------------------------------------------------------------------
__global__ __launch_bounds__(256, 1)
void weff_kernel(const float* __restrict__ Wk, const float* __restrict__ La,
                 const float* __restrict__ Lb) {
    __shared__ float s_k[32][33], s_a[32][33], s_b[32][33], s_o[32][33];
    int tx = threadIdx.x, ty = threadIdx.y;
    int f0 = blockIdx.x * 32, h0 = blockIdx.y * 32;
#pragma unroll
    for (int r = ty; r < 32; r += 8) {
        s_k[r][tx] = Wk[(size_t)(h0 + r) * F_DIM + f0 + tx];
        s_b[r][tx] = Lb[(size_t)r * F_DIM + f0 + tx];
        s_a[r][tx] = La[(size_t)(h0 + r) * 32 + tx];
    }
    __syncthreads();
#pragma unroll
    for (int hh = ty; hh < 32; hh += 8) {
        float acc = s_k[hh][tx];
#pragma unroll
        for (int r = 0; r < 32; r++) acc += s_a[hh][r] * s_b[r][tx];
        s_o[hh][tx] = acc;
    }
    __syncthreads();
    {
        int f = f0 + tx;
        int h = h0 + ty * 4;
        uint2 o;
        o.x = packh2(s_o[ty * 4 + 0][tx], s_o[ty * 4 + 1][tx]);
        o.y = packh2(s_o[ty * 4 + 2][tx], s_o[ty * 4 + 3][tx]);
        size_t tile = (size_t)(f >> 7) * 64 + (h >> 6);
        uint32_t off = ((uint32_t)(f & 127) * 128 + (uint32_t)(h & 63) * 2) ^
                       ((uint32_t)(f & 7) << 4);
        *reinterpret_cast<uint2*>(reinterpret_cast<char*>(g_WT) +
                                  (tile << 14) + off) = o;
    }
}

// ---------------------------------------------------------------------------
// Kernel 3: persistent fp16 mma.sync GEMM; producer bulk-copy pipeline
// continues across tile boundaries (epilogue overlaps next tile's loads).
// ---------------------------------------------------------------------------
__global__ __launch_bounds__(256, 2)
void gemm_kernel(const float* __restrict__ bias, float* __restrict__ out) {
    extern __shared__ char smem[];
    const uint32_t sb = smem_u32(smem);
    const uint32_t MB = sb + MBAR_OFF;
    const int tid = threadIdx.x;
    const int wid = tid >> 5, lane = tid & 31;
    const int l2 = lane >> 2, l3 = lane & 3;
    const int mwarp = (wid >> 2) * 64;
    const int nwarp = (wid & 3) * 32;

    const int myTiles = (NTILES - (int)blockIdx.x + GRID - 1) / GRID;
    const int totalChunks = myTiles * NCHUNK;

    if (tid == 0) {
#pragma unroll
        for (int s = 0; s < NSTAGE; s++) {
            MBAR_INIT(MB + 16 * s, 1u);      // full (expect_tx arrive)
            MBAR_INIT(MB + 16 * s + 8, 8u);  // empty (1 arrive per warp)
        }
    }
    __syncthreads();

    // ---- producer state (live in warp 0 only) ----
    int pchunk = 0;                // next global chunk to issue
    int ps = 0;                    // its stage
    uint32_t ppar = 1u;            // empty-wait parity for that stage use
    const char* pA = nullptr;
    const char* pB = nullptr;

    auto issue_one = [&]() {
        if (pchunk >= totalChunks) return;
        const int j = pchunk & (NCHUNK - 1);
        if (j == 0) {
            const int tileIdx = (int)blockIdx.x + (pchunk >> 6) * GRID;
            const int rr = tileIdx & 255, gg = tileIdx >> 8;
            const int mt = gg * 8 + (rr & 7);
            const int nt = rr >> 3;
            pA = reinterpret_cast<const char*>(g_Y) + ((size_t)mt << 20);
            pB = reinterpret_cast<const char*>(g_WT) + ((size_t)nt << 20);
        }
        if (lane == 0) {
            const uint32_t fullb = MB + 16 * ps;
            MBAR_WAIT(fullb + 8, ppar);
            asm volatile("mbarrier.arrive.expect_tx.shared.b64 _, [%0], %1;"
                         :: "r"(fullb), "r"(STAGE_TX) : "memory");
            const uint32_t st = sb + ps * STAGE_BYTES;
            bulk_cp(st, pA + ((size_t)j << 14), TILE_BYTES, fullb);
            bulk_cp(st + A_STAGE_BYTES, pB + ((size_t)j << 14), TILE_BYTES, fullb);
        }
        pchunk++;
        if (++ps == NSTAGE) { ps = 0; ppar ^= 1u; }
    };

    // ldmatrix addressing: 128B pitch + XOR swizzle
    const uint32_t aRowB = (uint32_t)(mwarp + (lane & 15)) * 128;
    const uint32_t aSel  = ((uint32_t)(lane >> 4)) << 4;
    const uint32_t bRowB = (uint32_t)(nwarp + (lane & 7) + ((lane >> 4) << 3)) * 128;
    const uint32_t bSel  = ((uint32_t)((lane >> 3) & 1)) << 4;
    const uint32_t swzA  = ((uint32_t)(lane & 7)) << 4;

    // ---- consumer state ----
    int cs = 0;
    uint32_t cpar = 0u;

    if (wid == 0) { issue_one(); issue_one(); }   // lookahead = 2

    float acc[4][4][4];

#pragma unroll 1
    for (int tl = 0; tl < myTiles; tl++) {
        const int tileIdx = (int)blockIdx.x + tl * GRID;
        const int rr = tileIdx & 255, gg = tileIdx >> 8;
        const int mt = gg * 8 + (rr & 7);
        const int nt = rr >> 3;
        const size_t m0 = (size_t)mt * BM, n0 = (size_t)nt * BN;

#pragma unroll
        for (int mi = 0; mi < 4; mi++)
#pragma unroll
            for (int ni = 0; ni < 4; ni++)
#pragma unroll
                for (int q = 0; q < 4; q++) acc[mi][ni][q] = 0.f;

#pragma unroll 1
        for (int c = 0; c < NCHUNK; c++) {
            if (wid == 0) issue_one();            // issue chunk n+2
            const uint32_t fullb = MB + 16 * cs;
            MBAR_WAIT(fullb, cpar);
            const uint32_t stA = sb + cs * STAGE_BYTES;
            const uint32_t stB = stA + A_STAGE_BYTES;
#pragma unroll
            for (int ks = 0; ks < 4; ks++) {
                const uint32_t kaoff = (((uint32_t)ks * 32 + aSel) ^ swzA);
                const uint32_t kboff = (((uint32_t)ks * 32 + bSel) ^ swzA);
                uint32_t af[4][4];
#pragma unroll
                for (int mi = 0; mi < 4; mi++)
                    ldsm_x4(af[mi], stA + aRowB + (uint32_t)mi * 2048 + kaoff);
                uint32_t bf[2][4];
#pragma unroll
                for (int p = 0; p < 2; p++)
                    ldsm_x4(bf[p], stB + bRowB + (uint32_t)p * 2048 + kboff);
#pragma unroll
                for (int mi = 0; mi < 4; mi++)
#pragma unroll
                    for (int p = 0; p < 2; p++) {
                        mma_f16(acc[mi][2 * p],     af[mi][0], af[mi][1],
                                af[mi][2], af[mi][3], bf[p][0], bf[p][1]);
                        mma_f16(acc[mi][2 * p + 1], af[mi][0], af[mi][1],
                                af[mi][2], af[mi][3], bf[p][2], bf[p][3]);
                    }
            }
            __syncwarp();
            if (lane == 0)
                asm volatile("mbarrier.arrive.shared.b64 _, [%0];"
                             :: "r"(fullb + 8) : "memory");
            if (++cs == NSTAGE) { cs = 0; cpar ^= 1u; }
        }

        // ---- epilogue (no smem; overlaps producer's next-tile loads) ----
        const float* bptr = bias + n0 + nwarp + 2 * l3;
#pragma unroll
        for (int ni = 0; ni < 4; ni++) {
            float bv0 = __ldg(bptr + ni * 8);
            float bv1 = __ldg(bptr + ni * 8 + 1);
            size_t gn = n0 + nwarp + (size_t)ni * 8 + 2 * l3;
#pragma unroll
            for (int mi = 0; mi < 4; mi++) {
                size_t gm = m0 + mwarp + (size_t)mi * 16 + l2;
                float2 v0 = make_float2(acc[mi][ni][0] + bv0, acc[mi][ni][1] + bv1);
                float2 v1 = make_float2(acc[mi][ni][2] + bv0, acc[mi][ni][3] + bv1);
                *reinterpret_cast<float2*>(out + gm * F_DIM + gn) = v0;
                *reinterpret_cast<float2*>(out + (gm + 8) * F_DIM + gn) = v1;
            }
        }
    }
}

// ---------------------------------------------------------------------------
extern "C" void kernel_launch(void* const* d_in, const int* in_sizes, int n_in,
                              void* d_out, int out_size) {
    (void)in_sizes; (void)n_in; (void)out_size;
    const float* x       = (const float*)d_in[0];
    const float* scale   = (const float*)d_in[1];
    const float* ln_bias = (const float*)d_in[2];
    const float* kern    = (const float*)d_in[3];
    const float* la      = (const float*)d_in[4];
    const float* lb      = (const float*)d_in[5];
    const float* bias    = (const float*)d_in[6];
    float* out = (float*)d_out;

    cudaFuncSetAttribute(gemm_kernel,
                         cudaFuncAttributeMaxDynamicSharedMemorySize, GEMM_SMEM);

    ln_kernel<<<M_DIM, 256>>>(x, scale, ln_bias);
    weff_kernel<<<dim3(F_DIM / 32, H_DIM / 32), dim3(32, 8)>>>(kern, la, lb);
    gemm_kernel<<<GRID, 256, GEMM_SMEM>>>(bias, out);
}

// round 12
// speedup vs baseline: 1.1019x; 1.1019x over previous
#include <cuda_runtime.h>
#include <cuda_fp16.h>
#include <cstdint>

// ---------------------------------------------------------------------------
// LayerNormDenseGeneral: out = LN(x) @ (kernel + lora_a@lora_b) + bias
// M=8192, K=H=4096, N=F=4096, R=32
// compute_103 build (no tcgen05). fp16 mma.sync m16n8k16 + ldmatrix.x4.
// R12: GEMM reverted to R10 exactly (655us; R11's persistent rewrite lost
// compile-time stage constants and regressed). New: LN + weff fused into one
// launch (disjoint data, neither saturates HBM alone) to cut prep serialization.
// ---------------------------------------------------------------------------

#define H_DIM 4096
#define F_DIM 4096
#define M_DIM 8192

#define BM 128
#define BN 128
#define BK 64
#define NCHUNK (H_DIM / BK)                   // 64
#define TILE_BYTES 16384                      // 128 rows * 128 B
#define A_STAGE_BYTES TILE_BYTES
#define STAGE_BYTES (2 * TILE_BYTES)          // 32768 (A + B)
#define NSTAGE 3
#define MBAR_OFF (NSTAGE * STAGE_BYTES)       // 98304
#define GEMM_SMEM (MBAR_OFF + 64)             // 98368 -> 2 CTAs/SM
#define STAGE_TX 32768u

#define WEFF_BLOCKS 16384                     // (4096/32)*(4096/32)
#define PREP_BLOCKS (WEFF_BLOCKS + M_DIM)     // + 8192 LN rows

__device__ __align__(16) __half g_Y[(size_t)M_DIM * H_DIM];   // tiled+swizzled
__device__ __align__(16) __half g_WT[(size_t)F_DIM * H_DIM];  // tiled+swizzled

// ---------------------------------------------------------------------------
__device__ __forceinline__ uint32_t smem_u32(const void* p) {
    uint32_t a;
    asm("{ .reg .u64 t; cvta.to.shared.u64 t, %1; cvt.u32.u64 %0, t; }"
        : "=r"(a) : "l"(p));
    return a;
}

__device__ __forceinline__ void ldsm_x4(uint32_t* r, uint32_t addr) {
    asm volatile("ldmatrix.sync.aligned.m8n8.x4.shared.b16 {%0,%1,%2,%3}, [%4];"
                 : "=r"(r[0]), "=r"(r[1]), "=r"(r[2]), "=r"(r[3]) : "r"(addr));
}

__device__ __forceinline__ uint32_t packh2(float lo, float hi) {
    __half2 h = __floats2half2_rn(lo, hi);
    return *reinterpret_cast<uint32_t*>(&h);
}

__device__ __forceinline__ void mma_f16(float* d,
                                        uint32_t a0, uint32_t a1,
                                        uint32_t a2, uint32_t a3,
                                        uint32_t b0, uint32_t b1) {
    asm volatile(
        "mma.sync.aligned.m16n8k16.row.col.f32.f16.f16.f32 "
        "{%0,%1,%2,%3}, {%4,%5,%6,%7}, {%8,%9}, {%0,%1,%2,%3};"
        : "+f"(d[0]), "+f"(d[1]), "+f"(d[2]), "+f"(d[3])
        : "r"(a0), "r"(a1), "r"(a2), "r"(a3), "r"(b0), "r"(b1));
}

__device__ __forceinline__ void bulk_cp(uint32_t dst, const void* src,
                                        uint32_t bytes, uint32_t mbar) {
    asm volatile(
        "cp.async.bulk.shared::cluster.global.mbarrier::complete_tx::bytes "
        "[%0], [%1], %2, [%3];"
        :: "r"(dst), "l"(__cvta_generic_to_global(src)), "r"(bytes), "r"(mbar)
        : "memory");
}

#define MBAR_INIT(addr, cnt) \
    asm volatile("mbarrier.init.shared.b64 [%0], %1;" :: "r"(addr), "r"(cnt) : "memory")

#define MBAR_WAIT(addr, parity) do {                                         \
    uint32_t _m = (addr); uint32_t _p = (parity); uint32_t _d;               \
    asm volatile(                                                            \
        "{\n\t.reg .pred p;\n\t"                                             \
        "mbarrier.try_wait.parity.acquire.cta.shared::cta.b64 p, [%1], %2;\n\t" \
        "selp.b32 %0, 1, 0, p;\n\t}"                                         \
        : "=r"(_d) : "r"(_m), "r"(_p) : "memory");                           \
    if (!_d) {                                                               \
        asm volatile(                                                        \
            "{\n\t.reg .pred P1;\n\t"                                        \
            "WL_%=:\n\t"                                                     \
            "mbarrier.try_wait.parity.acquire.cta.shared::cta.b64 P1, [%0], %1, 0x989680;\n\t" \
            "@P1 bra.uni WD_%=;\n\t"                                         \
            "bra.uni WL_%=;\n\t"                                             \
            "WD_%=:\n\t}"                                                    \
            :: "r"(_m), "r"(_p) : "memory");                                 \
    }                                                                        \
} while (0)

// ---------------------------------------------------------------------------
// Fused prep kernel.
// blocks [0, WEFF_BLOCKS): W_eff tile (32x32) -> g_WT (tiled + swizzled)
// blocks [WEFF_BLOCKS, PREP_BLOCKS): LayerNorm row -> g_Y (tiled + swizzled)
// ---------------------------------------------------------------------------
__global__ __launch_bounds__(256, 1)
void prep_kernel(const float* __restrict__ x, const float* __restrict__ gamma,
                 const float* __restrict__ beta,
                 const float* __restrict__ Wk, const float* __restrict__ La,
                 const float* __restrict__ Lb) {
    __shared__ float s_k[32][33], s_a[32][33], s_b[32][33], s_o[32][33];

    if (blockIdx.x < WEFF_BLOCKS) {
        // ---------------- weff tile ----------------
        const int b = blockIdx.x;
        const int tx = threadIdx.x & 31, ty = threadIdx.x >> 5;
        const int f0 = (b & 127) * 32, h0 = (b >> 7) * 32;
#pragma unroll
        for (int r = ty; r < 32; r += 8) {
            s_k[r][tx] = Wk[(size_t)(h0 + r) * F_DIM + f0 + tx];
            s_b[r][tx] = Lb[(size_t)r * F_DIM + f0 + tx];
            s_a[r][tx] = La[(size_t)(h0 + r) * 32 + tx];
        }
        __syncthreads();
#pragma unroll
        for (int hh = ty; hh < 32; hh += 8) {
            float acc = s_k[hh][tx];
#pragma unroll
            for (int r = 0; r < 32; r++) acc += s_a[hh][r] * s_b[r][tx];
            s_o[hh][tx] = acc;
        }
        __syncthreads();
        {
            int f = f0 + tx;
            int h = h0 + ty * 4;
            uint2 o;
            o.x = packh2(s_o[ty * 4 + 0][tx], s_o[ty * 4 + 1][tx]);
            o.y = packh2(s_o[ty * 4 + 2][tx], s_o[ty * 4 + 3][tx]);
            size_t tile = (size_t)(f >> 7) * 64 + (h >> 6);
            uint32_t off = ((uint32_t)(f & 127) * 128 + (uint32_t)(h & 63) * 2) ^
                           ((uint32_t)(f & 7) << 4);
            *reinterpret_cast<uint2*>(reinterpret_cast<char*>(g_WT) +
                                      (tile << 14) + off) = o;
        }
        return;
    }

    // ---------------- LayerNorm row ----------------
    float* sm = &s_k[0][0];                    // reuse shared
    const int row = blockIdx.x - WEFF_BLOCKS;
    const float4* xr = reinterpret_cast<const float4*>(x) + (size_t)row * (H_DIM / 4);
    float4 v[2][2];
    float s = 0.f;
#pragma unroll
    for (int i = 0; i < 2; i++) {
        int q = (threadIdx.x + i * 256) * 2;
        v[i][0] = xr[q];
        v[i][1] = xr[q + 1];
        s += (v[i][0].x + v[i][0].y) + (v[i][0].z + v[i][0].w);
        s += (v[i][1].x + v[i][1].y) + (v[i][1].z + v[i][1].w);
    }
#pragma unroll
    for (int o = 16; o > 0; o >>= 1) s += __shfl_xor_sync(0xffffffffu, s, o);
    if ((threadIdx.x & 31) == 0) sm[threadIdx.x >> 5] = s;
    __syncthreads();
    float tot = 0.f;
#pragma unroll
    for (int k = 0; k < 8; k++) tot += sm[k];
    float mean = tot * (1.0f / H_DIM);
    __syncthreads();

    float s2 = 0.f;
#pragma unroll
    for (int i = 0; i < 2; i++)
#pragma unroll
        for (int h = 0; h < 2; h++) {
            float a = v[i][h].x - mean, b = v[i][h].y - mean;
            float c = v[i][h].z - mean, d = v[i][h].w - mean;
            s2 += (a * a + b * b) + (c * c + d * d);
        }
#pragma unroll
    for (int o = 16; o > 0; o >>= 1) s2 += __shfl_xor_sync(0xffffffffu, s2, o);
    if ((threadIdx.x & 31) == 0) sm[threadIdx.x >> 5] = s2;
    __syncthreads();
    float t2 = 0.f;
#pragma unroll
    for (int k = 0; k < 8; k++) t2 += sm[k];
    float rstd = rsqrtf(t2 * (1.0f / H_DIM) + 1e-6f);

    const float4* g4 = reinterpret_cast<const float4*>(gamma);
    const float4* b4 = reinterpret_cast<const float4*>(beta);
    char* base = reinterpret_cast<char*>(g_Y);
    const size_t tr = (size_t)(row >> 7) * 64;
    const uint32_t rowoff = (uint32_t)(row & 127) * 128;
    const uint32_t rswz = (uint32_t)(row & 7) << 4;
#pragma unroll
    for (int i = 0; i < 2; i++) {
        int q = (threadIdx.x + i * 256) * 2;
        int k0 = q * 4;
        float4 g0 = g4[q], g1 = g4[q + 1];
        float4 c0 = b4[q], c1 = b4[q + 1];
        uint4 o;
        o.x = packh2((v[i][0].x - mean) * rstd * g0.x + c0.x,
                     (v[i][0].y - mean) * rstd * g0.y + c0.y);
        o.y = packh2((v[i][0].z - mean) * rstd * g0.z + c0.z,
                     (v[i][0].w - mean) * rstd * g0.w + c0.w);
        o.z = packh2((v[i][1].x - mean) * rstd * g1.x + c1.x,
                     (v[i][1].y - mean) * rstd * g1.y + c1.y);
        o.w = packh2((v[i][1].z - mean) * rstd * g1.z + c1.z,
                     (v[i][1].w - mean) * rstd * g1.w + c1.w);
        int j = k0 >> 6;
        uint32_t off = (rowoff + (uint32_t)(k0 & 63) * 2) ^ rswz;
        *reinterpret_cast<uint4*>(base + ((tr + j) << 14) + off) = o;
    }
}

// ---------------------------------------------------------------------------
// GEMM (identical to R10, 655us): fp16 mma.sync, 2 bulk copies/chunk,
// mbarrier pipeline, CTA 128x128, 8 warps 2(M)x4(N), 3 stages, 2 CTAs/SM.
// ---------------------------------------------------------------------------
__global__ __launch_bounds__(256, 2)
void gemm_kernel(const float* __restrict__ bias, float* __restrict__ out) {
    extern __shared__ char smem[];
    const uint32_t sb = smem_u32(smem);
    const uint32_t MB = sb + MBAR_OFF;
    const int tid = threadIdx.x;
    const int wid = tid >> 5, lane = tid & 31;
    const int l2 = lane >> 2, l3 = lane & 3;
    const int mwarp = (wid >> 2) * 64;
    const int nwarp = (wid & 3) * 32;

    const int r = blockIdx.x & 255;
    const int g = blockIdx.x >> 8;
    const int mt = g * 8 + (r & 7);
    const int nt = r >> 3;
    const size_t m0 = (size_t)mt * BM, n0 = (size_t)nt * BN;
    const char* Abase = reinterpret_cast<const char*>(g_Y) + ((size_t)mt << 20);
    const char* Bbase = reinterpret_cast<const char*>(g_WT) + ((size_t)nt << 20);

    if (tid == 0) {
#pragma unroll
        for (int s = 0; s < NSTAGE; s++) {
            MBAR_INIT(MB + 16 * s, 1u);      // full (expect_tx arrive)
            MBAR_INIT(MB + 16 * s + 8, 8u);  // empty (1 arrive per warp)
        }
    }
    __syncthreads();

    auto issue = [&](int j, int s, uint32_t emptyParity) {
        if (lane == 0) {
            const uint32_t fullb = MB + 16 * s;
            MBAR_WAIT(fullb + 8, emptyParity);
            asm volatile("mbarrier.arrive.expect_tx.shared.b64 _, [%0], %1;"
                         :: "r"(fullb), "r"(STAGE_TX) : "memory");
            const uint32_t st = sb + s * STAGE_BYTES;
            bulk_cp(st, Abase + ((size_t)j << 14), TILE_BYTES, fullb);
            bulk_cp(st + A_STAGE_BYTES, Bbase + ((size_t)j << 14), TILE_BYTES, fullb);
        }
    };

    float acc[4][4][4];
#pragma unroll
    for (int mi = 0; mi < 4; mi++)
#pragma unroll
        for (int ni = 0; ni < 4; ni++)
#pragma unroll
            for (int q = 0; q < 4; q++) acc[mi][ni][q] = 0.f;

    // ldmatrix addressing: 128B pitch + XOR swizzle
    const uint32_t aRowB = (uint32_t)(mwarp + (lane & 15)) * 128;
    const uint32_t aSel  = ((uint32_t)(lane >> 4)) << 4;
    const uint32_t bRowB = (uint32_t)(nwarp + (lane & 7) + ((lane >> 4) << 3)) * 128;
    const uint32_t bSel  = ((uint32_t)((lane >> 3) & 1)) << 4;
    const uint32_t swzA  = ((uint32_t)(lane & 7)) << 4;

    auto compute = [&](int s, uint32_t parity) {
        const uint32_t fullb = MB + 16 * s;
        MBAR_WAIT(fullb, parity);
        const uint32_t stA = sb + s * STAGE_BYTES;
        const uint32_t stB = stA + A_STAGE_BYTES;
#pragma unroll
        for (int ks = 0; ks < 4; ks++) {
            const uint32_t kaoff = (((uint32_t)ks * 32 + aSel) ^ swzA);
            const uint32_t kboff = (((uint32_t)ks * 32 + bSel) ^ swzA);
            uint32_t af[4][4];
#pragma unroll
            for (int mi = 0; mi < 4; mi++)
                ldsm_x4(af[mi], stA + aRowB + (uint32_t)mi * 2048 + kaoff);
            uint32_t bf[2][4];
#pragma unroll
            for (int p = 0; p < 2; p++)
                ldsm_x4(bf[p], stB + bRowB + (uint32_t)p * 2048 + kboff);
#pragma unroll
            for (int mi = 0; mi < 4; mi++)
#pragma unroll
                for (int p = 0; p < 2; p++) {
                    mma_f16(acc[mi][2 * p],     af[mi][0], af[mi][1],
                            af[mi][2], af[mi][3], bf[p][0], bf[p][1]);
                    mma_f16(acc[mi][2 * p + 1], af[mi][0], af[mi][1],
                            af[mi][2], af[mi][3], bf[p][2], bf[p][3]);
                }
        }
        __syncwarp();
        if (lane == 0)
            asm volatile("mbarrier.arrive.shared.b64 _, [%0];"
                         :: "r"(fullb + 8) : "memory");
    };

    // chunk c -> stage c%3, consumer parity (c/3)&1.
    // producer refill for stage use u waits empty parity (u+1)&1.
    if (wid == 0) { issue(0, 0, 1u); issue(1, 1, 1u); }

#pragma unroll 1
    for (int t = 0; t < 21; t++) {
        const int j = 3 * t;
        const uint32_t cp = (uint32_t)(t & 1), cpn = cp ^ 1u;
        if (wid == 0) issue(j + 2, 2, cpn);
        compute(0, cp);
        if (wid == 0 && j + 3 < NCHUNK) issue(j + 3, 0, cp);
        compute(1, cp);
        if (wid == 0 && j + 4 < NCHUNK) issue(j + 4, 1, cp);
        compute(2, cp);
    }
    compute(0, 1u);   // chunk 63

    // ---- epilogue: direct gmem stores, 32B-aligned float2 segments ----
    const float* bptr = bias + n0 + nwarp + 2 * l3;
#pragma unroll
    for (int ni = 0; ni < 4; ni++) {
        float bv0 = __ldg(bptr + ni * 8);
        float bv1 = __ldg(bptr + ni * 8 + 1);
        size_t gn = n0 + nwarp + (size_t)ni * 8 + 2 * l3;
#pragma unroll
        for (int mi = 0; mi < 4; mi++) {
            size_t gm = m0 + mwarp + (size_t)mi * 16 + l2;
            float2 v0 = make_float2(acc[mi][ni][0] + bv0, acc[mi][ni][1] + bv1);
            float2 v1 = make_float2(acc[mi][ni][2] + bv0, acc[mi][ni][3] + bv1);
            *reinterpret_cast<float2*>(out + gm * F_DIM + gn) = v0;
            *reinterpret_cast<float2*>(out + (gm + 8) * F_DIM + gn) = v1;
        }
    }
}

// ---------------------------------------------------------------------------
extern "C" void kernel_launch(void* const* d_in, const int* in_sizes, int n_in,
                              void* d_out, int out_size) {
    (void)in_sizes; (void)n_in; (void)out_size;
    const float* x       = (const float*)d_in[0];
    const float* scale   = (const float*)d_in[1];
    const float* ln_bias = (const float*)d_in[2];
    const float* kern    = (const float*)d_in[3];
    const float* la      = (const float*)d_in[4];
    const float* lb      = (const float*)d_in[5];
    const float* bias    = (const float*)d_in[6];
    float* out = (float*)d_out;

    cudaFuncSetAttribute(gemm_kernel,
                         cudaFuncAttributeMaxDynamicSharedMemorySize, GEMM_SMEM);

    prep_kernel<<<PREP_BLOCKS, 256>>>(x, scale, ln_bias, kern, la, lb);
    gemm_kernel<<<(M_DIM / BM) * (F_DIM / BN), 256, GEMM_SMEM>>>(bias, out);
}

// round 13
// speedup vs baseline: 1.1034x; 1.0013x over previous
#include <cuda_runtime.h>
#include <cuda_fp16.h>
#include <cstdint>

// ---------------------------------------------------------------------------
// LayerNormDenseGeneral: out = LN(x) @ (kernel + lora_a@lora_b) + bias
// M=8192, K=H=4096, N=F=4096, R=32
// compute_103 build (no tcgen05). fp16 mma.sync m16n8k16 + ldmatrix.x4.
// R13 (on R12, 641us / GEMM 505.9us @ tensor 89.2%):
//  - early stage release: empty-barrier arrive right after the chunk's last
//    ldmatrix (before the final MMA block) -> producer refills ~300cyc sooner
//  - relaxed parity wait for the producer's empty-wait (async-proxy only)
// ---------------------------------------------------------------------------

#define H_DIM 4096
#define F_DIM 4096
#define M_DIM 8192

#define BM 128
#define BN 128
#define BK 64
#define NCHUNK (H_DIM / BK)                   // 64
#define TILE_BYTES 16384                      // 128 rows * 128 B
#define A_STAGE_BYTES TILE_BYTES
#define STAGE_BYTES (2 * TILE_BYTES)          // 32768 (A + B)
#define NSTAGE 3
#define MBAR_OFF (NSTAGE * STAGE_BYTES)       // 98304
#define GEMM_SMEM (MBAR_OFF + 64)             // 98368 -> 2 CTAs/SM
#define STAGE_TX 32768u

#define WEFF_BLOCKS 16384                     // (4096/32)*(4096/32)
#define PREP_BLOCKS (WEFF_BLOCKS + M_DIM)     // + 8192 LN rows

__device__ __align__(16) __half g_Y[(size_t)M_DIM * H_DIM];   // tiled+swizzled
__device__ __align__(16) __half g_WT[(size_t)F_DIM * H_DIM];  // tiled+swizzled

// ---------------------------------------------------------------------------
__device__ __forceinline__ uint32_t smem_u32(const void* p) {
    uint32_t a;
    asm("{ .reg .u64 t; cvta.to.shared.u64 t, %1; cvt.u32.u64 %0, t; }"
        : "=r"(a) : "l"(p));
    return a;
}

__device__ __forceinline__ void ldsm_x4(uint32_t* r, uint32_t addr) {
    asm volatile("ldmatrix.sync.aligned.m8n8.x4.shared.b16 {%0,%1,%2,%3}, [%4];"
                 : "=r"(r[0]), "=r"(r[1]), "=r"(r[2]), "=r"(r[3]) : "r"(addr));
}

__device__ __forceinline__ uint32_t packh2(float lo, float hi) {
    __half2 h = __floats2half2_rn(lo, hi);
    return *reinterpret_cast<uint32_t*>(&h);
}

__device__ __forceinline__ void mma_f16(float* d,
                                        uint32_t a0, uint32_t a1,
                                        uint32_t a2, uint32_t a3,
                                        uint32_t b0, uint32_t b1) {
    asm volatile(
        "mma.sync.aligned.m16n8k16.row.col.f32.f16.f16.f32 "
        "{%0,%1,%2,%3}, {%4,%5,%6,%7}, {%8,%9}, {%0,%1,%2,%3};"
        : "+f"(d[0]), "+f"(d[1]), "+f"(d[2]), "+f"(d[3])
        : "r"(a0), "r"(a1), "r"(a2), "r"(a3), "r"(b0), "r"(b1));
}

__device__ __forceinline__ void bulk_cp(uint32_t dst, const void* src,
                                        uint32_t bytes, uint32_t mbar) {
    asm volatile(
        "cp.async.bulk.shared::cluster.global.mbarrier::complete_tx::bytes "
        "[%0], [%1], %2, [%3];"
        :: "r"(dst), "l"(__cvta_generic_to_global(src)), "r"(bytes), "r"(mbar)
        : "memory");
}

#define MBAR_INIT(addr, cnt) \
    asm volatile("mbarrier.init.shared.b64 [%0], %1;" :: "r"(addr), "r"(cnt) : "memory")

#define MBAR_WAIT(addr, parity) do {                                         \
    uint32_t _m = (addr); uint32_t _p = (parity); uint32_t _d;               \
    asm volatile(                                                            \
        "{\n\t.reg .pred p;\n\t"                                             \
        "mbarrier.try_wait.parity.acquire.cta.shared::cta.b64 p, [%1], %2;\n\t" \
        "selp.b32 %0, 1, 0, p;\n\t}"                                         \
        : "=r"(_d) : "r"(_m), "r"(_p) : "memory");                           \
    if (!_d) {                                                               \
        asm volatile(                                                        \
            "{\n\t.reg .pred P1;\n\t"                                        \
            "WL_%=:\n\t"                                                     \
            "mbarrier.try_wait.parity.acquire.cta.shared::cta.b64 P1, [%0], %1, 0x989680;\n\t" \
            "@P1 bra.uni WD_%=;\n\t"                                         \
            "bra.uni WL_%=;\n\t"                                             \
            "WD_%=:\n\t}"                                                    \
            :: "r"(_m), "r"(_p) : "memory");                                 \
    }                                                                        \
} while (0)

#define MBAR_WAIT_RELAXED(addr, parity) do {                                 \
    uint32_t _m = (addr); uint32_t _p = (parity); uint32_t _d;               \
    asm volatile(                                                            \
        "{\n\t.reg .pred p;\n\t"                                             \
        "mbarrier.try_wait.parity.relaxed.cta.shared::cta.b64 p, [%1], %2;\n\t" \
        "selp.b32 %0, 1, 0, p;\n\t}"                                         \
        : "=r"(_d) : "r"(_m), "r"(_p) : "memory");                           \
    if (!_d) {                                                               \
        asm volatile(                                                        \
            "{\n\t.reg .pred P1;\n\t"                                        \
            "WL_%=:\n\t"                                                     \
            "mbarrier.try_wait.parity.relaxed.cta.shared::cta.b64 P1, [%0], %1, 0x989680;\n\t" \
            "@P1 bra.uni WD_%=;\n\t"                                         \
            "bra.uni WL_%=;\n\t"                                             \
            "WD_%=:\n\t}"                                                    \
            :: "r"(_m), "r"(_p) : "memory");                                 \
    }                                                                        \
} while (0)

// ---------------------------------------------------------------------------
// Fused prep kernel.
// blocks [0, WEFF_BLOCKS): W_eff tile (32x32) -> g_WT (tiled + swizzled)
// blocks [WEFF_BLOCKS, PREP_BLOCKS): LayerNorm row -> g_Y (tiled + swizzled)
// ---------------------------------------------------------------------------
__global__ __launch_bounds__(256, 1)
void prep_kernel(const float* __restrict__ x, const float* __restrict__ gamma,
                 const float* __restrict__ beta,
                 const float* __restrict__ Wk, const float* __restrict__ La,
                 const float* __restrict__ Lb) {
    __shared__ float s_k[32][33], s_a[32][33], s_b[32][33], s_o[32][33];

    if (blockIdx.x < WEFF_BLOCKS) {
        // ---------------- weff tile ----------------
        const int b = blockIdx.x;
        const int tx = threadIdx.x & 31, ty = threadIdx.x >> 5;
        const int f0 = (b & 127) * 32, h0 = (b >> 7) * 32;
#pragma unroll
        for (int r = ty; r < 32; r += 8) {
            s_k[r][tx] = Wk[(size_t)(h0 + r) * F_DIM + f0 + tx];
            s_b[r][tx] = Lb[(size_t)r * F_DIM + f0 + tx];
            s_a[r][tx] = La[(size_t)(h0 + r) * 32 + tx];
        }
        __syncthreads();
#pragma unroll
        for (int hh = ty; hh < 32; hh += 8) {
            float acc = s_k[hh][tx];
#pragma unroll
            for (int r = 0; r < 32; r++) acc += s_a[hh][r] * s_b[r][tx];
            s_o[hh][tx] = acc;
        }
        __syncthreads();
        {
            int f = f0 + tx;
            int h = h0 + ty * 4;
            uint2 o;
            o.x = packh2(s_o[ty * 4 + 0][tx], s_o[ty * 4 + 1][tx]);
            o.y = packh2(s_o[ty * 4 + 2][tx], s_o[ty * 4 + 3][tx]);
            size_t tile = (size_t)(f >> 7) * 64 + (h >> 6);
            uint32_t off = ((uint32_t)(f & 127) * 128 + (uint32_t)(h & 63) * 2) ^
                           ((uint32_t)(f & 7) << 4);
            *reinterpret_cast<uint2*>(reinterpret_cast<char*>(g_WT) +
                                      (tile << 14) + off) = o;
        }
        return;
    }

    // ---------------- LayerNorm row ----------------
    float* sm = &s_k[0][0];                    // reuse shared
    const int row = blockIdx.x - WEFF_BLOCKS;
    const float4* xr = reinterpret_cast<const float4*>(x) + (size_t)row * (H_DIM / 4);
    float4 v[2][2];
    float s = 0.f;
#pragma unroll
    for (int i = 0; i < 2; i++) {
        int q = (threadIdx.x + i * 256) * 2;
        v[i][0] = xr[q];
        v[i][1] = xr[q + 1];
        s += (v[i][0].x + v[i][0].y) + (v[i][0].z + v[i][0].w);
        s += (v[i][1].x + v[i][1].y) + (v[i][1].z + v[i][1].w);
    }
#pragma unroll
    for (int o = 16; o > 0; o >>= 1) s += __shfl_xor_sync(0xffffffffu, s, o);
    if ((threadIdx.x & 31) == 0) sm[threadIdx.x >> 5] = s;
    __syncthreads();
    float tot = 0.f;
#pragma unroll
    for (int k = 0; k < 8; k++) tot += sm[k];
    float mean = tot * (1.0f / H_DIM);
    __syncthreads();

    float s2 = 0.f;
#pragma unroll
    for (int i = 0; i < 2; i++)
#pragma unroll
        for (int h = 0; h < 2; h++) {
            float a = v[i][h].x - mean, b = v[i][h].y - mean;
            float c = v[i][h].z - mean, d = v[i][h].w - mean;
            s2 += (a * a + b * b) + (c * c + d * d);
        }
#pragma unroll
    for (int o = 16; o > 0; o >>= 1) s2 += __shfl_xor_sync(0xffffffffu, s2, o);
    if ((threadIdx.x & 31) == 0) sm[threadIdx.x >> 5] = s2;
    __syncthreads();
    float t2 = 0.f;
#pragma unroll
    for (int k = 0; k < 8; k++) t2 += sm[k];
    float rstd = rsqrtf(t2 * (1.0f / H_DIM) + 1e-6f);

    const float4* g4 = reinterpret_cast<const float4*>(gamma);
    const float4* b4 = reinterpret_cast<const float4*>(beta);
    char* base = reinterpret_cast<char*>(g_Y);
    const size_t tr = (size_t)(row >> 7) * 64;
    const uint32_t rowoff = (uint32_t)(row & 127) * 128;
    const uint32_t rswz = (uint32_t)(row & 7) << 4;
#pragma unroll
    for (int i = 0; i < 2; i++) {
        int q = (threadIdx.x + i * 256) * 2;
        int k0 = q * 4;
        float4 g0 = g4[q], g1 = g4[q + 1];
        float4 c0 = b4[q], c1 = b4[q + 1];
        uint4 o;
        o.x = packh2((v[i][0].x - mean) * rstd * g0.x + c0.x,
                     (v[i][0].y - mean) * rstd * g0.y + c0.y);
        o.y = packh2((v[i][0].z - mean) * rstd * g0.z + c0.z,
                     (v[i][0].w - mean) * rstd * g0.w + c0.w);
        o.z = packh2((v[i][1].x - mean) * rstd * g1.x + c1.x,
                     (v[i][1].y - mean) * rstd * g1.y + c1.y);
        o.w = packh2((v[i][1].z - mean) * rstd * g1.z + c1.z,
                     (v[i][1].w - mean) * rstd * g1.w + c1.w);
        int j = k0 >> 6;
        uint32_t off = (rowoff + (uint32_t)(k0 & 63) * 2) ^ rswz;
        *reinterpret_cast<uint4*>(base + ((tr + j) << 14) + off) = o;
    }
}

// ---------------------------------------------------------------------------
// GEMM: fp16 mma.sync, 2 bulk copies/chunk, mbarrier pipeline,
// CTA 128x128, 8 warps 2(M)x4(N), 3 stages, 2 CTAs/SM.
// R13: early empty-arrive (post-last-LDSM), relaxed producer wait.
// ---------------------------------------------------------------------------
__global__ __launch_bounds__(256, 2)
void gemm_kernel(const float* __restrict__ bias, float* __restrict__ out) {
    extern __shared__ char smem[];
    const uint32_t sb = smem_u32(smem);
    const uint32_t MB = sb + MBAR_OFF;
    const int tid = threadIdx.x;
    const int wid = tid >> 5, lane = tid & 31;
    const int l2 = lane >> 2, l3 = lane & 3;
    const int mwarp = (wid >> 2) * 64;
    const int nwarp = (wid & 3) * 32;

    const int r = blockIdx.x & 255;
    const int g = blockIdx.x >> 8;
    const int mt = g * 8 + (r & 7);
    const int nt = r >> 3;
    const size_t m0 = (size_t)mt * BM, n0 = (size_t)nt * BN;
    const char* Abase = reinterpret_cast<const char*>(g_Y) + ((size_t)mt << 20);
    const char* Bbase = reinterpret_cast<const char*>(g_WT) + ((size_t)nt << 20);

    if (tid == 0) {
#pragma unroll
        for (int s = 0; s < NSTAGE; s++) {
            MBAR_INIT(MB + 16 * s, 1u);      // full (expect_tx arrive)
            MBAR_INIT(MB + 16 * s + 8, 8u);  // empty (1 arrive per warp)
        }
    }
    __syncthreads();

    auto issue = [&](int j, int s, uint32_t emptyParity) {
        if (lane == 0) {
            const uint32_t fullb = MB + 16 * s;
            MBAR_WAIT_RELAXED(fullb + 8, emptyParity);
            asm volatile("mbarrier.arrive.expect_tx.shared.b64 _, [%0], %1;"
                         :: "r"(fullb), "r"(STAGE_TX) : "memory");
            const uint32_t st = sb + s * STAGE_BYTES;
            bulk_cp(st, Abase + ((size_t)j << 14), TILE_BYTES, fullb);
            bulk_cp(st + A_STAGE_BYTES, Bbase + ((size_t)j << 14), TILE_BYTES, fullb);
        }
    };

    float acc[4][4][4];
#pragma unroll
    for (int mi = 0; mi < 4; mi++)
#pragma unroll
        for (int ni = 0; ni < 4; ni++)
#pragma unroll
            for (int q = 0; q < 4; q++) acc[mi][ni][q] = 0.f;

    // ldmatrix addressing: 128B pitch + XOR swizzle
    const uint32_t aRowB = (uint32_t)(mwarp + (lane & 15)) * 128;
    const uint32_t aSel  = ((uint32_t)(lane >> 4)) << 4;
    const uint32_t bRowB = (uint32_t)(nwarp + (lane & 7) + ((lane >> 4) << 3)) * 128;
    const uint32_t bSel  = ((uint32_t)((lane >> 3) & 1)) << 4;
    const uint32_t swzA  = ((uint32_t)(lane & 7)) << 4;

    auto compute = [&](int s, uint32_t parity) {
        const uint32_t fullb = MB + 16 * s;
        MBAR_WAIT(fullb, parity);
        const uint32_t stA = sb + s * STAGE_BYTES;
        const uint32_t stB = stA + A_STAGE_BYTES;
#pragma unroll
        for (int ks = 0; ks < 4; ks++) {
            const uint32_t kaoff = (((uint32_t)ks * 32 + aSel) ^ swzA);
            const uint32_t kboff = (((uint32_t)ks * 32 + bSel) ^ swzA);
            uint32_t af[4][4];
#pragma unroll
            for (int mi = 0; mi < 4; mi++)
                ldsm_x4(af[mi], stA + aRowB + (uint32_t)mi * 2048 + kaoff);
            uint32_t bf[2][4];
#pragma unroll
            for (int p = 0; p < 2; p++)
                ldsm_x4(bf[p], stB + bRowB + (uint32_t)p * 2048 + kboff);
            if (ks == 3) {
                // all smem reads of this chunk are issued -> release the stage
                __syncwarp();
                if (lane == 0)
                    asm volatile("mbarrier.arrive.shared.b64 _, [%0];"
                                 :: "r"(fullb + 8) : "memory");
            }
#pragma unroll
            for (int mi = 0; mi < 4; mi++)
#pragma unroll
                for (int p = 0; p < 2; p++) {
                    mma_f16(acc[mi][2 * p],     af[mi][0], af[mi][1],
                            af[mi][2], af[mi][3], bf[p][0], bf[p][1]);
                    mma_f16(acc[mi][2 * p + 1], af[mi][0], af[mi][1],
                            af[mi][2], af[mi][3], bf[p][2], bf[p][3]);
                }
        }
    };

    // chunk c -> stage c%3, consumer parity (c/3)&1.
    // producer refill for stage use u waits empty parity (u+1)&1.
    if (wid == 0) { issue(0, 0, 1u); issue(1, 1, 1u); }

#pragma unroll 1
    for (int t = 0; t < 21; t++) {
        const int j = 3 * t;
        const uint32_t cp = (uint32_t)(t & 1), cpn = cp ^ 1u;
        if (wid == 0) issue(j + 2, 2, cpn);
        compute(0, cp);
        if (wid == 0 && j + 3 < NCHUNK) issue(j + 3, 0, cp);
        compute(1, cp);
        if (wid == 0 && j + 4 < NCHUNK) issue(j + 4, 1, cp);
        compute(2, cp);
    }
    compute(0, 1u);   // chunk 63

    // ---- epilogue: direct gmem stores, 32B-aligned float2 segments ----
    const float* bptr = bias + n0 + nwarp + 2 * l3;
#pragma unroll
    for (int ni = 0; ni < 4; ni++) {
        float bv0 = __ldg(bptr + ni * 8);
        float bv1 = __ldg(bptr + ni * 8 + 1);
        size_t gn = n0 + nwarp + (size_t)ni * 8 + 2 * l3;
#pragma unroll
        for (int mi = 0; mi < 4; mi++) {
            size_t gm = m0 + mwarp + (size_t)mi * 16 + l2;
            float2 v0 = make_float2(acc[mi][ni][0] + bv0, acc[mi][ni][1] + bv1);
            float2 v1 = make_float2(acc[mi][ni][2] + bv0, acc[mi][ni][3] + bv1);
            *reinterpret_cast<float2*>(out + gm * F_DIM + gn) = v0;
            *reinterpret_cast<float2*>(out + (gm + 8) * F_DIM + gn) = v1;
        }
    }
}

// ---------------------------------------------------------------------------
extern "C" void kernel_launch(void* const* d_in, const int* in_sizes, int n_in,
                              void* d_out, int out_size) {
    (void)in_sizes; (void)n_in; (void)out_size;
    const float* x       = (const float*)d_in[0];
    const float* scale   = (const float*)d_in[1];
    const float* ln_bias = (const float*)d_in[2];
    const float* kern    = (const float*)d_in[3];
    const float* la      = (const float*)d_in[4];
    const float* lb      = (const float*)d_in[5];
    const float* bias    = (const float*)d_in[6];
    float* out = (float*)d_out;

    cudaFuncSetAttribute(gemm_kernel,
                         cudaFuncAttributeMaxDynamicSharedMemorySize, GEMM_SMEM);

    prep_kernel<<<PREP_BLOCKS, 256>>>(x, scale, ln_bias, kern, la, lb);
    gemm_kernel<<<(M_DIM / BM) * (F_DIM / BN), 256, GEMM_SMEM>>>(bias, out);
}

// round 14
// speedup vs baseline: 1.1280x; 1.0223x over previous
#include <cuda_runtime.h>
#include <cuda_fp16.h>
#include <cstdint>

// ---------------------------------------------------------------------------
// LayerNormDenseGeneral: out = LN(x) @ (kernel + lora_a@lora_b) + bias
// M=8192, K=H=4096, N=F=4096, R=32
// compute_103 build (no tcgen05). fp16 mma.sync m16n8k16 + ldmatrix.x4.
// R14 (on R13, 640us / GEMM 508us @ tensor 89%): weff tile compute
// vectorized -- s_bT transposed (pitch 36, conflict-free float4), thread
// computes 4 h-outputs via float4 dot blocks: 40 LDS.128 vs 256 scalar LDS.
// s_o staging + 2nd __syncthreads deleted. GEMM/LN unchanged.
// ---------------------------------------------------------------------------

#define H_DIM 4096
#define F_DIM 4096
#define M_DIM 8192

#define BM 128
#define BN 128
#define BK 64
#define NCHUNK (H_DIM / BK)                   // 64
#define TILE_BYTES 16384                      // 128 rows * 128 B
#define A_STAGE_BYTES TILE_BYTES
#define STAGE_BYTES (2 * TILE_BYTES)          // 32768 (A + B)
#define NSTAGE 3
#define MBAR_OFF (NSTAGE * STAGE_BYTES)       // 98304
#define GEMM_SMEM (MBAR_OFF + 64)             // 98368 -> 2 CTAs/SM
#define STAGE_TX 32768u

#define WEFF_BLOCKS 16384                     // (4096/32)*(4096/32)
#define PREP_BLOCKS (WEFF_BLOCKS + M_DIM)     // + 8192 LN rows

__device__ __align__(16) __half g_Y[(size_t)M_DIM * H_DIM];   // tiled+swizzled
__device__ __align__(16) __half g_WT[(size_t)F_DIM * H_DIM];  // tiled+swizzled

// ---------------------------------------------------------------------------
__device__ __forceinline__ uint32_t smem_u32(const void* p) {
    uint32_t a;
    asm("{ .reg .u64 t; cvta.to.shared.u64 t, %1; cvt.u32.u64 %0, t; }"
        : "=r"(a) : "l"(p));
    return a;
}

__device__ __forceinline__ void ldsm_x4(uint32_t* r, uint32_t addr) {
    asm volatile("ldmatrix.sync.aligned.m8n8.x4.shared.b16 {%0,%1,%2,%3}, [%4];"
                 : "=r"(r[0]), "=r"(r[1]), "=r"(r[2]), "=r"(r[3]) : "r"(addr));
}

__device__ __forceinline__ uint32_t packh2(float lo, float hi) {
    __half2 h = __floats2half2_rn(lo, hi);
    return *reinterpret_cast<uint32_t*>(&h);
}

__device__ __forceinline__ void mma_f16(float* d,
                                        uint32_t a0, uint32_t a1,
                                        uint32_t a2, uint32_t a3,
                                        uint32_t b0, uint32_t b1) {
    asm volatile(
        "mma.sync.aligned.m16n8k16.row.col.f32.f16.f16.f32 "
        "{%0,%1,%2,%3}, {%4,%5,%6,%7}, {%8,%9}, {%0,%1,%2,%3};"
        : "+f"(d[0]), "+f"(d[1]), "+f"(d[2]), "+f"(d[3])
        : "r"(a0), "r"(a1), "r"(a2), "r"(a3), "r"(b0), "r"(b1));
}

__device__ __forceinline__ void bulk_cp(uint32_t dst, const void* src,
                                        uint32_t bytes, uint32_t mbar) {
    asm volatile(
        "cp.async.bulk.shared::cluster.global.mbarrier::complete_tx::bytes "
        "[%0], [%1], %2, [%3];"
        :: "r"(dst), "l"(__cvta_generic_to_global(src)), "r"(bytes), "r"(mbar)
        : "memory");
}

#define MBAR_INIT(addr, cnt) \
    asm volatile("mbarrier.init.shared.b64 [%0], %1;" :: "r"(addr), "r"(cnt) : "memory")

#define MBAR_WAIT(addr, parity) do {                                         \
    uint32_t _m = (addr); uint32_t _p = (parity); uint32_t _d;               \
    asm volatile(                                                            \
        "{\n\t.reg .pred p;\n\t"                                             \
        "mbarrier.try_wait.parity.acquire.cta.shared::cta.b64 p, [%1], %2;\n\t" \
        "selp.b32 %0, 1, 0, p;\n\t}"                                         \
        : "=r"(_d) : "r"(_m), "r"(_p) : "memory");                           \
    if (!_d) {                                                               \
        asm volatile(                                                        \
            "{\n\t.reg .pred P1;\n\t"                                        \
            "WL_%=:\n\t"                                                     \
            "mbarrier.try_wait.parity.acquire.cta.shared::cta.b64 P1, [%0], %1, 0x989680;\n\t" \
            "@P1 bra.uni WD_%=;\n\t"                                         \
            "bra.uni WL_%=;\n\t"                                             \
            "WD_%=:\n\t}"                                                    \
            :: "r"(_m), "r"(_p) : "memory");                                 \
    }                                                                        \
} while (0)

#define MBAR_WAIT_RELAXED(addr, parity) do {                                 \
    uint32_t _m = (addr); uint32_t _p = (parity); uint32_t _d;               \
    asm volatile(                                                            \
        "{\n\t.reg .pred p;\n\t"                                             \
        "mbarrier.try_wait.parity.relaxed.cta.shared::cta.b64 p, [%1], %2;\n\t" \
        "selp.b32 %0, 1, 0, p;\n\t}"                                         \
        : "=r"(_d) : "r"(_m), "r"(_p) : "memory");                           \
    if (!_d) {                                                               \
        asm volatile(                                                        \
            "{\n\t.reg .pred P1;\n\t"                                        \
            "WL_%=:\n\t"                                                     \
            "mbarrier.try_wait.parity.relaxed.cta.shared::cta.b64 P1, [%0], %1, 0x989680;\n\t" \
            "@P1 bra.uni WD_%=;\n\t"                                         \
            "bra.uni WL_%=;\n\t"                                             \
            "WD_%=:\n\t}"                                                    \
            :: "r"(_m), "r"(_p) : "memory");                                 \
    }                                                                        \
} while (0)

// ---------------------------------------------------------------------------
// Fused prep kernel.
// blocks [0, WEFF_BLOCKS): W_eff tile (32x32) -> g_WT (tiled + swizzled)
// blocks [WEFF_BLOCKS, PREP_BLOCKS): LayerNorm row -> g_Y (tiled + swizzled)
// ---------------------------------------------------------------------------
__global__ __launch_bounds__(256, 1)
void prep_kernel(const float* __restrict__ x, const float* __restrict__ gamma,
                 const float* __restrict__ beta,
                 const float* __restrict__ Wk, const float* __restrict__ La,
                 const float* __restrict__ Lb) {
    __shared__ float s_k[32][33];
    __shared__ float s_a[32][36];     // [h][r], float4-aligned pitch
    __shared__ float s_bT[32][36];    // [f][r] (transposed lora_b tile)

    if (blockIdx.x < WEFF_BLOCKS) {
        // ---------------- weff tile (vectorized) ----------------
        const int b = blockIdx.x;
        const int tx = threadIdx.x & 31, ty = threadIdx.x >> 5;
        const int f0 = (b & 127) * 32, h0 = (b >> 7) * 32;
#pragma unroll
        for (int r = ty; r < 32; r += 8) {
            s_k[r][tx] = Wk[(size_t)(h0 + r) * F_DIM + f0 + tx];
            s_a[r][tx] = La[(size_t)(h0 + r) * 32 + tx];
            s_bT[tx][r] = Lb[(size_t)r * F_DIM + f0 + tx];
        }
        __syncthreads();

        float acc[4];
#pragma unroll
        for (int q = 0; q < 4; q++) acc[q] = s_k[ty * 4 + q][tx];
#pragma unroll
        for (int r0 = 0; r0 < 32; r0 += 4) {
            float4 b4 = *reinterpret_cast<const float4*>(&s_bT[tx][r0]);
#pragma unroll
            for (int q = 0; q < 4; q++) {
                float4 a4 = *reinterpret_cast<const float4*>(&s_a[ty * 4 + q][r0]);
                acc[q] += a4.x * b4.x + a4.y * b4.y + a4.z * b4.z + a4.w * b4.w;
            }
        }

        // direct write (acc rows already match output layout)
        {
            int f = f0 + tx;
            int h = h0 + ty * 4;
            uint2 o;
            o.x = packh2(acc[0], acc[1]);
            o.y = packh2(acc[2], acc[3]);
            size_t tile = (size_t)(f >> 7) * 64 + (h >> 6);
            uint32_t off = ((uint32_t)(f & 127) * 128 + (uint32_t)(h & 63) * 2) ^
                           ((uint32_t)(f & 7) << 4);
            *reinterpret_cast<uint2*>(reinterpret_cast<char*>(g_WT) +
                                      (tile << 14) + off) = o;
        }
        return;
    }

    // ---------------- LayerNorm row ----------------
    float* sm = &s_k[0][0];                    // reuse shared
    const int row = blockIdx.x - WEFF_BLOCKS;
    const float4* xr = reinterpret_cast<const float4*>(x) + (size_t)row * (H_DIM / 4);
    float4 v[2][2];
    float s = 0.f;
#pragma unroll
    for (int i = 0; i < 2; i++) {
        int q = (threadIdx.x + i * 256) * 2;
        v[i][0] = xr[q];
        v[i][1] = xr[q + 1];
        s += (v[i][0].x + v[i][0].y) + (v[i][0].z + v[i][0].w);
        s += (v[i][1].x + v[i][1].y) + (v[i][1].z + v[i][1].w);
    }
#pragma unroll
    for (int o = 16; o > 0; o >>= 1) s += __shfl_xor_sync(0xffffffffu, s, o);
    if ((threadIdx.x & 31) == 0) sm[threadIdx.x >> 5] = s;
    __syncthreads();
    float tot = 0.f;
#pragma unroll
    for (int k = 0; k < 8; k++) tot += sm[k];
    float mean = tot * (1.0f / H_DIM);
    __syncthreads();

    float s2 = 0.f;
#pragma unroll
    for (int i = 0; i < 2; i++)
#pragma unroll
        for (int h = 0; h < 2; h++) {
            float a = v[i][h].x - mean, b = v[i][h].y - mean;
            float c = v[i][h].z - mean, d = v[i][h].w - mean;
            s2 += (a * a + b * b) + (c * c + d * d);
        }
#pragma unroll
    for (int o = 16; o > 0; o >>= 1) s2 += __shfl_xor_sync(0xffffffffu, s2, o);
    if ((threadIdx.x & 31) == 0) sm[threadIdx.x >> 5] = s2;
    __syncthreads();
    float t2 = 0.f;
#pragma unroll
    for (int k = 0; k < 8; k++) t2 += sm[k];
    float rstd = rsqrtf(t2 * (1.0f / H_DIM) + 1e-6f);

    const float4* g4 = reinterpret_cast<const float4*>(gamma);
    const float4* b4 = reinterpret_cast<const float4*>(beta);
    char* base = reinterpret_cast<char*>(g_Y);
    const size_t tr = (size_t)(row >> 7) * 64;
    const uint32_t rowoff = (uint32_t)(row & 127) * 128;
    const uint32_t rswz = (uint32_t)(row & 7) << 4;
#pragma unroll
    for (int i = 0; i < 2; i++) {
        int q = (threadIdx.x + i * 256) * 2;
        int k0 = q * 4;
        float4 g0 = g4[q], g1 = g4[q + 1];
        float4 c0 = b4[q], c1 = b4[q + 1];
        uint4 o;
        o.x = packh2((v[i][0].x - mean) * rstd * g0.x + c0.x,
                     (v[i][0].y - mean) * rstd * g0.y + c0.y);
        o.y = packh2((v[i][0].z - mean) * rstd * g0.z + c0.z,
                     (v[i][0].w - mean) * rstd * g0.w + c0.w);
        o.z = packh2((v[i][1].x - mean) * rstd * g1.x + c1.x,
                     (v[i][1].y - mean) * rstd * g1.y + c1.y);
        o.w = packh2((v[i][1].z - mean) * rstd * g1.z + c1.z,
                     (v[i][1].w - mean) * rstd * g1.w + c1.w);
        int j = k0 >> 6;
        uint32_t off = (rowoff + (uint32_t)(k0 & 63) * 2) ^ rswz;
        *reinterpret_cast<uint4*>(base + ((tr + j) << 14) + off) = o;
    }
}

// ---------------------------------------------------------------------------
// GEMM: fp16 mma.sync, 2 bulk copies/chunk, mbarrier pipeline,
// CTA 128x128, 8 warps 2(M)x4(N), 3 stages, 2 CTAs/SM. (identical to R13)
// ---------------------------------------------------------------------------
__global__ __launch_bounds__(256, 2)
void gemm_kernel(const float* __restrict__ bias, float* __restrict__ out) {
    extern __shared__ char smem[];
    const uint32_t sb = smem_u32(smem);
    const uint32_t MB = sb + MBAR_OFF;
    const int tid = threadIdx.x;
    const int wid = tid >> 5, lane = tid & 31;
    const int l2 = lane >> 2, l3 = lane & 3;
    const int mwarp = (wid >> 2) * 64;
    const int nwarp = (wid & 3) * 32;

    const int r = blockIdx.x & 255;
    const int g = blockIdx.x >> 8;
    const int mt = g * 8 + (r & 7);
    const int nt = r >> 3;
    const size_t m0 = (size_t)mt * BM, n0 = (size_t)nt * BN;
    const char* Abase = reinterpret_cast<const char*>(g_Y) + ((size_t)mt << 20);
    const char* Bbase = reinterpret_cast<const char*>(g_WT) + ((size_t)nt << 20);

    if (tid == 0) {
#pragma unroll
        for (int s = 0; s < NSTAGE; s++) {
            MBAR_INIT(MB + 16 * s, 1u);      // full (expect_tx arrive)
            MBAR_INIT(MB + 16 * s + 8, 8u);  // empty (1 arrive per warp)
        }
    }
    __syncthreads();

    auto issue = [&](int j, int s, uint32_t emptyParity) {
        if (lane == 0) {
            const uint32_t fullb = MB + 16 * s;
            MBAR_WAIT_RELAXED(fullb + 8, emptyParity);
            asm volatile("mbarrier.arrive.expect_tx.shared.b64 _, [%0], %1;"
                         :: "r"(fullb), "r"(STAGE_TX) : "memory");
            const uint32_t st = sb + s * STAGE_BYTES;
            bulk_cp(st, Abase + ((size_t)j << 14), TILE_BYTES, fullb);
            bulk_cp(st + A_STAGE_BYTES, Bbase + ((size_t)j << 14), TILE_BYTES, fullb);
        }
    };

    float acc[4][4][4];
#pragma unroll
    for (int mi = 0; mi < 4; mi++)
#pragma unroll
        for (int ni = 0; ni < 4; ni++)
#pragma unroll
            for (int q = 0; q < 4; q++) acc[mi][ni][q] = 0.f;

    // ldmatrix addressing: 128B pitch + XOR swizzle
    const uint32_t aRowB = (uint32_t)(mwarp + (lane & 15)) * 128;
    const uint32_t aSel  = ((uint32_t)(lane >> 4)) << 4;
    const uint32_t bRowB = (uint32_t)(nwarp + (lane & 7) + ((lane >> 4) << 3)) * 128;
    const uint32_t bSel  = ((uint32_t)((lane >> 3) & 1)) << 4;
    const uint32_t swzA  = ((uint32_t)(lane & 7)) << 4;

    auto compute = [&](int s, uint32_t parity) {
        const uint32_t fullb = MB + 16 * s;
        MBAR_WAIT(fullb, parity);
        const uint32_t stA = sb + s * STAGE_BYTES;
        const uint32_t stB = stA + A_STAGE_BYTES;
#pragma unroll
        for (int ks = 0; ks < 4; ks++) {
            const uint32_t kaoff = (((uint32_t)ks * 32 + aSel) ^ swzA);
            const uint32_t kboff = (((uint32_t)ks * 32 + bSel) ^ swzA);
            uint32_t af[4][4];
#pragma unroll
            for (int mi = 0; mi < 4; mi++)
                ldsm_x4(af[mi], stA + aRowB + (uint32_t)mi * 2048 + kaoff);
            uint32_t bf[2][4];
#pragma unroll
            for (int p = 0; p < 2; p++)
                ldsm_x4(bf[p], stB + bRowB + (uint32_t)p * 2048 + kboff);
            if (ks == 3) {
                // all smem reads of this chunk are issued -> release the stage
                __syncwarp();
                if (lane == 0)
                    asm volatile("mbarrier.arrive.shared.b64 _, [%0];"
                                 :: "r"(fullb + 8) : "memory");
            }
#pragma unroll
            for (int mi = 0; mi < 4; mi++)
#pragma unroll
                for (int p = 0; p < 2; p++) {
                    mma_f16(acc[mi][2 * p],     af[mi][0], af[mi][1],
                            af[mi][2], af[mi][3], bf[p][0], bf[p][1]);
                    mma_f16(acc[mi][2 * p + 1], af[mi][0], af[mi][1],
                            af[mi][2], af[mi][3], bf[p][2], bf[p][3]);
                }
        }
    };

    // chunk c -> stage c%3, consumer parity (c/3)&1.
    // producer refill for stage use u waits empty parity (u+1)&1.
    if (wid == 0) { issue(0, 0, 1u); issue(1, 1, 1u); }

#pragma unroll 1
    for (int t = 0; t < 21; t++) {
        const int j = 3 * t;
        const uint32_t cp = (uint32_t)(t & 1), cpn = cp ^ 1u;
        if (wid == 0) issue(j + 2, 2, cpn);
        compute(0, cp);
        if (wid == 0 && j + 3 < NCHUNK) issue(j + 3, 0, cp);
        compute(1, cp);
        if (wid == 0 && j + 4 < NCHUNK) issue(j + 4, 1, cp);
        compute(2, cp);
    }
    compute(0, 1u);   // chunk 63

    // ---- epilogue: direct gmem stores, 32B-aligned float2 segments ----
    const float* bptr = bias + n0 + nwarp + 2 * l3;
#pragma unroll
    for (int ni = 0; ni < 4; ni++) {
        float bv0 = __ldg(bptr + ni * 8);
        float bv1 = __ldg(bptr + ni * 8 + 1);
        size_t gn = n0 + nwarp + (size_t)ni * 8 + 2 * l3;
#pragma unroll
        for (int mi = 0; mi < 4; mi++) {
            size_t gm = m0 + mwarp + (size_t)mi * 16 + l2;
            float2 v0 = make_float2(acc[mi][ni][0] + bv0, acc[mi][ni][1] + bv1);
            float2 v1 = make_float2(acc[mi][ni][2] + bv0, acc[mi][ni][3] + bv1);
            *reinterpret_cast<float2*>(out + gm * F_DIM + gn) = v0;
            *reinterpret_cast<float2*>(out + (gm + 8) * F_DIM + gn) = v1;
        }
    }
}

// ---------------------------------------------------------------------------
extern "C" void kernel_launch(void* const* d_in, const int* in_sizes, int n_in,
                              void* d_out, int out_size) {
    (void)in_sizes; (void)n_in; (void)out_size;
    const float* x       = (const float*)d_in[0];
    const float* scale   = (const float*)d_in[1];
    const float* ln_bias = (const float*)d_in[2];
    const float* kern    = (const float*)d_in[3];
    const float* la      = (const float*)d_in[4];
    const float* lb      = (const float*)d_in[5];
    const float* bias    = (const float*)d_in[6];
    float* out = (float*)d_out;

    cudaFuncSetAttribute(gemm_kernel,
                         cudaFuncAttributeMaxDynamicSharedMemorySize, GEMM_SMEM);

    prep_kernel<<<PREP_BLOCKS, 256>>>(x, scale, ln_bias, kern, la, lb);
    gemm_kernel<<<(M_DIM / BM) * (F_DIM / BN), 256, GEMM_SMEM>>>(bias, out);
}

// round 15
// speedup vs baseline: 1.1678x; 1.0353x over previous
#include <cuda_runtime.h>
#include <cuda_fp16.h>
#include <cstdint>

// ---------------------------------------------------------------------------
// LayerNormDenseGeneral: out = LN(x) @ (kernel + lora_a@lora_b) + bias
// M=8192, K=H=4096, N=F=4096, R=32
// compute_103 build (no tcgen05). fp16 mma.sync m16n8k16 + ldmatrix.x4.
// R15 (on R14, 626us / GEMM 509us @ tensor 89%): weff retiled to 32f x 64h
// blocks with smem-staged coalesced writes (full 128B sectors; old pattern
// was 8B-per-128B-stride = 4x write amplification). GEMM/LN unchanged.
// ---------------------------------------------------------------------------

#define H_DIM 4096
#define F_DIM 4096
#define M_DIM 8192

#define BM 128
#define BN 128
#define BK 64
#define NCHUNK (H_DIM / BK)                   // 64
#define TILE_BYTES 16384                      // 128 rows * 128 B
#define A_STAGE_BYTES TILE_BYTES
#define STAGE_BYTES (2 * TILE_BYTES)          // 32768 (A + B)
#define NSTAGE 3
#define MBAR_OFF (NSTAGE * STAGE_BYTES)       // 98304
#define GEMM_SMEM (MBAR_OFF + 64)             // 98368 -> 2 CTAs/SM
#define STAGE_TX 32768u

#define WEFF_BLOCKS 8192                      // (4096/32 f) * (4096/64 h)
#define PREP_BLOCKS (WEFF_BLOCKS + M_DIM)     // + 8192 LN rows

__device__ __align__(16) __half g_Y[(size_t)M_DIM * H_DIM];   // tiled+swizzled
__device__ __align__(16) __half g_WT[(size_t)F_DIM * H_DIM];  // tiled+swizzled

// ---------------------------------------------------------------------------
__device__ __forceinline__ uint32_t smem_u32(const void* p) {
    uint32_t a;
    asm("{ .reg .u64 t; cvta.to.shared.u64 t, %1; cvt.u32.u64 %0, t; }"
        : "=r"(a) : "l"(p));
    return a;
}

__device__ __forceinline__ void ldsm_x4(uint32_t* r, uint32_t addr) {
    asm volatile("ldmatrix.sync.aligned.m8n8.x4.shared.b16 {%0,%1,%2,%3}, [%4];"
                 : "=r"(r[0]), "=r"(r[1]), "=r"(r[2]), "=r"(r[3]) : "r"(addr));
}

__device__ __forceinline__ uint32_t packh2(float lo, float hi) {
    __half2 h = __floats2half2_rn(lo, hi);
    return *reinterpret_cast<uint32_t*>(&h);
}

__device__ __forceinline__ void mma_f16(float* d,
                                        uint32_t a0, uint32_t a1,
                                        uint32_t a2, uint32_t a3,
                                        uint32_t b0, uint32_t b1) {
    asm volatile(
        "mma.sync.aligned.m16n8k16.row.col.f32.f16.f16.f32 "
        "{%0,%1,%2,%3}, {%4,%5,%6,%7}, {%8,%9}, {%0,%1,%2,%3};"
        : "+f"(d[0]), "+f"(d[1]), "+f"(d[2]), "+f"(d[3])
        : "r"(a0), "r"(a1), "r"(a2), "r"(a3), "r"(b0), "r"(b1));
}

__device__ __forceinline__ void bulk_cp(uint32_t dst, const void* src,
                                        uint32_t bytes, uint32_t mbar) {
    asm volatile(
        "cp.async.bulk.shared::cluster.global.mbarrier::complete_tx::bytes "
        "[%0], [%1], %2, [%3];"
        :: "r"(dst), "l"(__cvta_generic_to_global(src)), "r"(bytes), "r"(mbar)
        : "memory");
}

#define MBAR_INIT(addr, cnt) \
    asm volatile("mbarrier.init.shared.b64 [%0], %1;" :: "r"(addr), "r"(cnt) : "memory")

#define MBAR_WAIT(addr, parity) do {                                         \
    uint32_t _m = (addr); uint32_t _p = (parity); uint32_t _d;               \
    asm volatile(                                                            \
        "{\n\t.reg .pred p;\n\t"                                             \
        "mbarrier.try_wait.parity.acquire.cta.shared::cta.b64 p, [%1], %2;\n\t" \
        "selp.b32 %0, 1, 0, p;\n\t}"                                         \
        : "=r"(_d) : "r"(_m), "r"(_p) : "memory");                           \
    if (!_d) {                                                               \
        asm volatile(                                                        \
            "{\n\t.reg .pred P1;\n\t"                                        \
            "WL_%=:\n\t"                                                     \
            "mbarrier.try_wait.parity.acquire.cta.shared::cta.b64 P1, [%0], %1, 0x989680;\n\t" \
            "@P1 bra.uni WD_%=;\n\t"                                         \
            "bra.uni WL_%=;\n\t"                                             \
            "WD_%=:\n\t}"                                                    \
            :: "r"(_m), "r"(_p) : "memory");                                 \
    }                                                                        \
} while (0)

#define MBAR_WAIT_RELAXED(addr, parity) do {                                 \
    uint32_t _m = (addr); uint32_t _p = (parity); uint32_t _d;               \
    asm volatile(                                                            \
        "{\n\t.reg .pred p;\n\t"                                             \
        "mbarrier.try_wait.parity.relaxed.cta.shared::cta.b64 p, [%1], %2;\n\t" \
        "selp.b32 %0, 1, 0, p;\n\t}"                                         \
        : "=r"(_d) : "r"(_m), "r"(_p) : "memory");                           \
    if (!_d) {                                                               \
        asm volatile(                                                        \
            "{\n\t.reg .pred P1;\n\t"                                        \
            "WL_%=:\n\t"                                                     \
            "mbarrier.try_wait.parity.relaxed.cta.shared::cta.b64 P1, [%0], %1, 0x989680;\n\t" \
            "@P1 bra.uni WD_%=;\n\t"                                         \
            "bra.uni WL_%=;\n\t"                                             \
            "WD_%=:\n\t}"                                                    \
            :: "r"(_m), "r"(_p) : "memory");                                 \
    }                                                                        \
} while (0)

// ---------------------------------------------------------------------------
// Fused prep kernel.
// blocks [0, WEFF_BLOCKS): W_eff 32f x 64h tile -> g_WT (tiled + swizzled)
// blocks [WEFF_BLOCKS, PREP_BLOCKS): LayerNorm row -> g_Y (tiled + swizzled)
// ---------------------------------------------------------------------------
__global__ __launch_bounds__(256, 1)
void prep_kernel(const float* __restrict__ x, const float* __restrict__ gamma,
                 const float* __restrict__ beta,
                 const float* __restrict__ Wk, const float* __restrict__ La,
                 const float* __restrict__ Lb) {
    __shared__ float s_k[64][33];                 // [h][f]
    __shared__ float s_a[64][36];                 // [h][r], float4 pitch
    __shared__ float s_bT[32][36];                // [f][r]
    __shared__ __align__(16) uint16_t s_o[32][72]; // [f][h] halves, 144B pitch

    if (blockIdx.x < WEFF_BLOCKS) {
        // ---------------- weff 32f x 64h tile ----------------
        const int b = blockIdx.x;
        const int tx = threadIdx.x & 31, ty = threadIdx.x >> 5;
        const int f0 = (b & 127) * 32, h0 = (b >> 7) * 64;
#pragma unroll
        for (int r = ty; r < 64; r += 8) {
            s_k[r][tx] = Wk[(size_t)(h0 + r) * F_DIM + f0 + tx];
            s_a[r][tx] = La[(size_t)(h0 + r) * 32 + tx];
        }
#pragma unroll
        for (int r = ty; r < 32; r += 8)
            s_bT[tx][r] = Lb[(size_t)r * F_DIM + f0 + tx];
        __syncthreads();

        // compute: thread (tx=f, ty=h-octet) -> 8 outputs h = ty*8+q
        float acc[8];
#pragma unroll
        for (int q = 0; q < 8; q++) acc[q] = s_k[ty * 8 + q][tx];
#pragma unroll
        for (int r0 = 0; r0 < 32; r0 += 4) {
            float4 b4 = *reinterpret_cast<const float4*>(&s_bT[tx][r0]);
#pragma unroll
            for (int q = 0; q < 8; q++) {
                float4 a4 = *reinterpret_cast<const float4*>(&s_a[ty * 8 + q][r0]);
                acc[q] += a4.x * b4.x + a4.y * b4.y + a4.z * b4.z + a4.w * b4.w;
            }
        }

        // stage packed halves: s_o[tx][ty*8 .. +7]
        {
            uint4 o;
            o.x = packh2(acc[0], acc[1]);
            o.y = packh2(acc[2], acc[3]);
            o.z = packh2(acc[4], acc[5]);
            o.w = packh2(acc[6], acc[7]);
            *reinterpret_cast<uint4*>(
                reinterpret_cast<char*>(&s_o[0][0]) + tx * 144 + ty * 16) = o;
        }
        __syncthreads();

        // coalesced write: 8 lanes cover one f-row's 128B
        {
            const int fy = threadIdx.x >> 3, hb = threadIdx.x & 7;
            uint4 v = *reinterpret_cast<const uint4*>(
                reinterpret_cast<const char*>(&s_o[0][0]) + fy * 144 + hb * 16);
            int f = f0 + fy, h = h0 + hb * 8;
            size_t tile = (size_t)(f >> 7) * 64 + (h >> 6);
            uint32_t off = ((uint32_t)(f & 127) * 128 + (uint32_t)(h & 63) * 2) ^
                           ((uint32_t)(f & 7) << 4);
            *reinterpret_cast<uint4*>(reinterpret_cast<char*>(g_WT) +
                                      (tile << 14) + off) = v;
        }
        return;
    }

    // ---------------- LayerNorm row ----------------
    float* sm = &s_k[0][0];                    // reuse shared
    const int row = blockIdx.x - WEFF_BLOCKS;
    const float4* xr = reinterpret_cast<const float4*>(x) + (size_t)row * (H_DIM / 4);
    float4 v[2][2];
    float s = 0.f;
#pragma unroll
    for (int i = 0; i < 2; i++) {
        int q = (threadIdx.x + i * 256) * 2;
        v[i][0] = xr[q];
        v[i][1] = xr[q + 1];
        s += (v[i][0].x + v[i][0].y) + (v[i][0].z + v[i][0].w);
        s += (v[i][1].x + v[i][1].y) + (v[i][1].z + v[i][1].w);
    }
#pragma unroll
    for (int o = 16; o > 0; o >>= 1) s += __shfl_xor_sync(0xffffffffu, s, o);
    if ((threadIdx.x & 31) == 0) sm[threadIdx.x >> 5] = s;
    __syncthreads();
    float tot = 0.f;
#pragma unroll
    for (int k = 0; k < 8; k++) tot += sm[k];
    float mean = tot * (1.0f / H_DIM);
    __syncthreads();

    float s2 = 0.f;
#pragma unroll
    for (int i = 0; i < 2; i++)
#pragma unroll
        for (int h = 0; h < 2; h++) {
            float a = v[i][h].x - mean, b = v[i][h].y - mean;
            float c = v[i][h].z - mean, d = v[i][h].w - mean;
            s2 += (a * a + b * b) + (c * c + d * d);
        }
#pragma unroll
    for (int o = 16; o > 0; o >>= 1) s2 += __shfl_xor_sync(0xffffffffu, s2, o);
    if ((threadIdx.x & 31) == 0) sm[threadIdx.x >> 5] = s2;
    __syncthreads();
    float t2 = 0.f;
#pragma unroll
    for (int k = 0; k < 8; k++) t2 += sm[k];
    float rstd = rsqrtf(t2 * (1.0f / H_DIM) + 1e-6f);

    const float4* g4 = reinterpret_cast<const float4*>(gamma);
    const float4* b4 = reinterpret_cast<const float4*>(beta);
    char* base = reinterpret_cast<char*>(g_Y);
    const size_t tr = (size_t)(row >> 7) * 64;
    const uint32_t rowoff = (uint32_t)(row & 127) * 128;
    const uint32_t rswz = (uint32_t)(row & 7) << 4;
#pragma unroll
    for (int i = 0; i < 2; i++) {
        int q = (threadIdx.x + i * 256) * 2;
        int k0 = q * 4;
        float4 g0 = g4[q], g1 = g4[q + 1];
        float4 c0 = b4[q], c1 = b4[q + 1];
        uint4 o;
        o.x = packh2((v[i][0].x - mean) * rstd * g0.x + c0.x,
                     (v[i][0].y - mean) * rstd * g0.y + c0.y);
        o.y = packh2((v[i][0].z - mean) * rstd * g0.z + c0.z,
                     (v[i][0].w - mean) * rstd * g0.w + c0.w);
        o.z = packh2((v[i][1].x - mean) * rstd * g1.x + c1.x,
                     (v[i][1].y - mean) * rstd * g1.y + c1.y);
        o.w = packh2((v[i][1].z - mean) * rstd * g1.z + c1.z,
                     (v[i][1].w - mean) * rstd * g1.w + c1.w);
        int j = k0 >> 6;
        uint32_t off = (rowoff + (uint32_t)(k0 & 63) * 2) ^ rswz;
        *reinterpret_cast<uint4*>(base + ((tr + j) << 14) + off) = o;
    }
}

// ---------------------------------------------------------------------------
// GEMM: fp16 mma.sync, 2 bulk copies/chunk, mbarrier pipeline,
// CTA 128x128, 8 warps 2(M)x4(N), 3 stages, 2 CTAs/SM. (identical to R14)
// ---------------------------------------------------------------------------
__global__ __launch_bounds__(256, 2)
void gemm_kernel(const float* __restrict__ bias, float* __restrict__ out) {
    extern __shared__ char smem[];
    const uint32_t sb = smem_u32(smem);
    const uint32_t MB = sb + MBAR_OFF;
    const int tid = threadIdx.x;
    const int wid = tid >> 5, lane = tid & 31;
    const int l2 = lane >> 2, l3 = lane & 3;
    const int mwarp = (wid >> 2) * 64;
    const int nwarp = (wid & 3) * 32;

    const int r = blockIdx.x & 255;
    const int g = blockIdx.x >> 8;
    const int mt = g * 8 + (r & 7);
    const int nt = r >> 3;
    const size_t m0 = (size_t)mt * BM, n0 = (size_t)nt * BN;
    const char* Abase = reinterpret_cast<const char*>(g_Y) + ((size_t)mt << 20);
    const char* Bbase = reinterpret_cast<const char*>(g_WT) + ((size_t)nt << 20);

    if (tid == 0) {
#pragma unroll
        for (int s = 0; s < NSTAGE; s++) {
            MBAR_INIT(MB + 16 * s, 1u);      // full (expect_tx arrive)
            MBAR_INIT(MB + 16 * s + 8, 8u);  // empty (1 arrive per warp)
        }
    }
    __syncthreads();

    auto issue = [&](int j, int s, uint32_t emptyParity) {
        if (lane == 0) {
            const uint32_t fullb = MB + 16 * s;
            MBAR_WAIT_RELAXED(fullb + 8, emptyParity);
            asm volatile("mbarrier.arrive.expect_tx.shared.b64 _, [%0], %1;"
                         :: "r"(fullb), "r"(STAGE_TX) : "memory");
            const uint32_t st = sb + s * STAGE_BYTES;
            bulk_cp(st, Abase + ((size_t)j << 14), TILE_BYTES, fullb);
            bulk_cp(st + A_STAGE_BYTES, Bbase + ((size_t)j << 14), TILE_BYTES, fullb);
        }
    };

    float acc[4][4][4];
#pragma unroll
    for (int mi = 0; mi < 4; mi++)
#pragma unroll
        for (int ni = 0; ni < 4; ni++)
#pragma unroll
            for (int q = 0; q < 4; q++) acc[mi][ni][q] = 0.f;

    // ldmatrix addressing: 128B pitch + XOR swizzle
    const uint32_t aRowB = (uint32_t)(mwarp + (lane & 15)) * 128;
    const uint32_t aSel  = ((uint32_t)(lane >> 4)) << 4;
    const uint32_t bRowB = (uint32_t)(nwarp + (lane & 7) + ((lane >> 4) << 3)) * 128;
    const uint32_t bSel  = ((uint32_t)((lane >> 3) & 1)) << 4;
    const uint32_t swzA  = ((uint32_t)(lane & 7)) << 4;

    auto compute = [&](int s, uint32_t parity) {
        const uint32_t fullb = MB + 16 * s;
        MBAR_WAIT(fullb, parity);
        const uint32_t stA = sb + s * STAGE_BYTES;
        const uint32_t stB = stA + A_STAGE_BYTES;
#pragma unroll
        for (int ks = 0; ks < 4; ks++) {
            const uint32_t kaoff = (((uint32_t)ks * 32 + aSel) ^ swzA);
            const uint32_t kboff = (((uint32_t)ks * 32 + bSel) ^ swzA);
            uint32_t af[4][4];
#pragma unroll
            for (int mi = 0; mi < 4; mi++)
                ldsm_x4(af[mi], stA + aRowB + (uint32_t)mi * 2048 + kaoff);
            uint32_t bf[2][4];
#pragma unroll
            for (int p = 0; p < 2; p++)
                ldsm_x4(bf[p], stB + bRowB + (uint32_t)p * 2048 + kboff);
            if (ks == 3) {
                // all smem reads of this chunk are issued -> release the stage
                __syncwarp();
                if (lane == 0)
                    asm volatile("mbarrier.arrive.shared.b64 _, [%0];"
                                 :: "r"(fullb + 8) : "memory");
            }
#pragma unroll
            for (int mi = 0; mi < 4; mi++)
#pragma unroll
                for (int p = 0; p < 2; p++) {
                    mma_f16(acc[mi][2 * p],     af[mi][0], af[mi][1],
                            af[mi][2], af[mi][3], bf[p][0], bf[p][1]);
                    mma_f16(acc[mi][2 * p + 1], af[mi][0], af[mi][1],
                            af[mi][2], af[mi][3], bf[p][2], bf[p][3]);
                }
        }
    };

    // chunk c -> stage c%3, consumer parity (c/3)&1.
    // producer refill for stage use u waits empty parity (u+1)&1.
    if (wid == 0) { issue(0, 0, 1u); issue(1, 1, 1u); }

#pragma unroll 1
    for (int t = 0; t < 21; t++) {
        const int j = 3 * t;
        const uint32_t cp = (uint32_t)(t & 1), cpn = cp ^ 1u;
        if (wid == 0) issue(j + 2, 2, cpn);
        compute(0, cp);
        if (wid == 0 && j + 3 < NCHUNK) issue(j + 3, 0, cp);
        compute(1, cp);
        if (wid == 0 && j + 4 < NCHUNK) issue(j + 4, 1, cp);
        compute(2, cp);
    }
    compute(0, 1u);   // chunk 63

    // ---- epilogue: direct gmem stores, 32B-aligned float2 segments ----
    const float* bptr = bias + n0 + nwarp + 2 * l3;
#pragma unroll
    for (int ni = 0; ni < 4; ni++) {
        float bv0 = __ldg(bptr + ni * 8);
        float bv1 = __ldg(bptr + ni * 8 + 1);
        size_t gn = n0 + nwarp + (size_t)ni * 8 + 2 * l3;
#pragma unroll
        for (int mi = 0; mi < 4; mi++) {
            size_t gm = m0 + mwarp + (size_t)mi * 16 + l2;
            float2 v0 = make_float2(acc[mi][ni][0] + bv0, acc[mi][ni][1] + bv1);
            float2 v1 = make_float2(acc[mi][ni][2] + bv0, acc[mi][ni][3] + bv1);
            *reinterpret_cast<float2*>(out + gm * F_DIM + gn) = v0;
            *reinterpret_cast<float2*>(out + (gm + 8) * F_DIM + gn) = v1;
        }
    }
}

// ---------------------------------------------------------------------------
extern "C" void kernel_launch(void* const* d_in, const int* in_sizes, int n_in,
                              void* d_out, int out_size) {
    (void)in_sizes; (void)n_in; (void)out_size;
    const float* x       = (const float*)d_in[0];
    const float* scale   = (const float*)d_in[1];
    const float* ln_bias = (const float*)d_in[2];
    const float* kern    = (const float*)d_in[3];
    const float* la      = (const float*)d_in[4];
    const float* lb      = (const float*)d_in[5];
    const float* bias    = (const float*)d_in[6];
    float* out = (float*)d_out;

    cudaFuncSetAttribute(gemm_kernel,
                         cudaFuncAttributeMaxDynamicSharedMemorySize, GEMM_SMEM);

    prep_kernel<<<PREP_BLOCKS, 256>>>(x, scale, ln_bias, kern, la, lb);
    gemm_kernel<<<(M_DIM / BM) * (F_DIM / BN), 256, GEMM_SMEM>>>(bias, out);
}